// round 17
// baseline (speedup 1.0000x reference)
#include <cuda_runtime.h>
#include <cuda_fp16.h>
#include <cstdint>

#define BATCH 4096
#define IDIM  512
#define ODIM  512
#define NB    16
#define KBASE 8192
#define KEXT  8704

#define BM 64
#define BN 256
#define BK 128
#define NKT 68             /* k-iters per tile */
#define BASIS_T 64         /* k-tiles < this: basis/weights; >=: silu */
#define NTHR 512
#define NTILES 128         /* 64 row-tiles x 2 col-strips */
#define GTOT (NTILES * NKT)/* 8704 global iter-units */
#define NCTA 148
#define TILE_A 16384       /* 64 rows x 128 halves x 2B */
#define TILE_BS 65536      /* 256 rows x 128 halves x 2B */

/* fused prep kernel block ranges (256 threads each) */
#define CV_UNITS 557056    /* (512*8192 + 512*512)/8 float4-pairs */
#define CV_HALF  278528
#define CV_BLOCKS 1088     /* CV_HALF / 256 */
#define XT_BLOCKS 2048     /* 16 x 128 tiles of 32x32 */
#define ZG_BLOCKS 512      /* 4096*512 floats / (4*4) / 256 */

// -------------------- device scratch --------------------
__device__ __half g_Wh [(size_t)ODIM * KBASE];
__device__ __half g_BWh[(size_t)ODIM * IDIM];
__device__ float  g_xT [(size_t)IDIM * BATCH];
__device__ float  g_gemm[(size_t)BATCH * ODIM];

// -------------------- helpers --------------------
__device__ __forceinline__ uint32_t smem_u32(const void* p) {
    uint32_t a;
    asm("{ .reg .u64 t; cvta.to.shared.u64 t, %1; cvt.u32.u64 %0, t; }" : "=r"(a) : "l"(p));
    return a;
}
__device__ __forceinline__ void cp_async16(uint32_t dst, const void* src) {
    asm volatile("cp.async.cg.shared.global [%0], [%1], 16;" :: "r"(dst), "l"(src));
}
__device__ __forceinline__ uint32_t pack_h2(float a, float b) {
    __half2 h = __floats2half2_rn(a, b);
    return *reinterpret_cast<uint32_t*>(&h);
}
__device__ __forceinline__ float fast_exp_neg_sq(float z) {
    float e;
    asm("ex2.approx.f32 %0, %1;" : "=f"(e) : "f"(z * z * -1.44269504f));
    return e;
}
__device__ __forceinline__ void red_add(float* p, float v) {
    asm volatile("red.global.add.f32 [%0], %1;" :: "l"(p), "f"(v) : "memory");
}

// -------------------- fused prep: weights->fp16 | x transpose | zero ------
__device__ __forceinline__ void cv_unit(const float* __restrict__ w,
                                        const float* __restrict__ bw, int i) {
    const int NW = ODIM * KBASE / 8;
    const float4* s; uint32_t* d; int j;
    if (i < NW) { s = (const float4*)w;  d = (uint32_t*)g_Wh;  j = i; }
    else        { s = (const float4*)bw; d = (uint32_t*)g_BWh; j = i - NW; }
    float4 a = s[2 * j], c = s[2 * j + 1];
    d[4 * j + 0] = pack_h2(a.x, a.y);
    d[4 * j + 1] = pack_h2(a.z, a.w);
    d[4 * j + 2] = pack_h2(c.x, c.y);
    d[4 * j + 3] = pack_h2(c.z, c.w);
}

__global__ void prep_all(const float* __restrict__ w, const float* __restrict__ bw,
                         const float* __restrict__ x) {
    int b = blockIdx.x;
    if (b < CV_BLOCKS) {
        int i = b * 256 + threadIdx.x;
        cv_unit(w, bw, i);                 // both units in flight -> 2x MLP
        cv_unit(w, bw, i + CV_HALF);
    } else if (b < CV_BLOCKS + XT_BLOCKS) {
        __shared__ float t[32][33];
        int bb = b - CV_BLOCKS;
        int i0 = (bb & 15) * 32, b0 = (bb >> 4) * 32;
        int tx = threadIdx.x & 31, ty = threadIdx.x >> 5;   // 32 x 8
#pragma unroll
        for (int r = ty; r < 32; r += 8)
            t[r][tx] = x[(size_t)(b0 + r) * IDIM + i0 + tx];
        __syncthreads();
#pragma unroll
        for (int r = ty; r < 32; r += 8)
            g_xT[(size_t)(i0 + r) * BATCH + b0 + tx] = t[tx][r];
    } else {
        int i = ((b - CV_BLOCKS - XT_BLOCKS) * 256 + threadIdx.x) * 4;
        float4 z = make_float4(0.f, 0.f, 0.f, 0.f);
        float4* p = (float4*)g_gemm;
        p[i] = z; p[i + 1] = z; p[i + 2] = z; p[i + 3] = z;
    }
}

// -------------------- GEMM pieces --------------------
__device__ __forceinline__ void gen_basis(float xv, uint32_t vals[8]) {
    float z0 = (xv + 2.0f) * 3.75f;
    float v[16];
#pragma unroll
    for (int j = 0; j < 16; j++) v[j] = fast_exp_neg_sq(z0 - (float)j);
#pragma unroll
    for (int p = 0; p < 8; p++) vals[p] = pack_h2(v[2 * p], v[2 * p + 1]);
}
__device__ __forceinline__ void gen_silu16(int l, int row, int iq, int m0,
                                           uint32_t vals[8]) {
    int ibase = (l - BASIS_T) * 128 + iq * 16;
#pragma unroll
    for (int p = 0; p < 8; p++) {
        float a = g_xT[(size_t)(ibase + 2 * p)     * BATCH + m0 + row];
        float b = g_xT[(size_t)(ibase + 2 * p + 1) * BATCH + m0 + row];
        float ea, eb;
        asm("ex2.approx.f32 %0, %1;" : "=f"(ea) : "f"(a * -1.44269504f));
        asm("ex2.approx.f32 %0, %1;" : "=f"(eb) : "f"(b * -1.44269504f));
        vals[p] = pack_h2(a / (1.0f + ea), b / (1.0f + eb));
    }
}
__device__ __forceinline__ void sts_vals(uint32_t aBase, int row, int iq,
                                         const uint32_t vals[8]) {
#pragma unroll
    for (int c = 0; c < 2; c++) {
        uint32_t u = row * 16 + ((iq * 2 + c) ^ (row & 7));   // 16B units
        asm volatile("st.shared.v4.b32 [%0], {%1,%2,%3,%4};"
                     :: "r"(aBase + u * 16),
                        "r"(vals[4 * c]), "r"(vals[4 * c + 1]),
                        "r"(vals[4 * c + 2]), "r"(vals[4 * c + 3]) : "memory");
    }
}
__device__ __forceinline__ void cp_B(int l, uint32_t bBase, int tid, int n0) {
    const __half* src; int ldb, ko;
    if (l < BASIS_T) { src = g_Wh;  ldb = KBASE; ko = l * BK; }
    else             { src = g_BWh; ldb = IDIM;  ko = (l - BASIS_T) * BK; }
#pragma unroll
    for (int q = 0; q < 8; q++) {
        int c   = tid + NTHR * q;
        int r   = c >> 4, u16 = c & 15;
        uint32_t u = r * 16 + (u16 ^ (r & 7));
        cp_async16(bBase + u * 16, src + (size_t)(n0 + r) * ldb + ko + u16 * 8);
    }
}

#define LDSM_X4(R, ADDR)                                                        \
    asm volatile("ldmatrix.sync.aligned.m8n8.x4.shared.b16 {%0,%1,%2,%3}, [%4];"\
                 : "=r"((R)[0]), "=r"((R)[1]), "=r"((R)[2]), "=r"((R)[3])       \
                 : "r"(ADDR))

#define MMA16816(ACC, A, B0, B1)                                                \
    asm volatile("mma.sync.aligned.m16n8k16.row.col.f32.f16.f16.f32 "           \
                 "{%0,%1,%2,%3}, {%4,%5,%6,%7}, {%8,%9}, {%0,%1,%2,%3};"        \
                 : "+f"((ACC)[0]), "+f"((ACC)[1]), "+f"((ACC)[2]), "+f"((ACC)[3])\
                 : "r"((A)[0]), "r"((A)[1]), "r"((A)[2]), "r"((A)[3]),          \
                   "r"(B0), "r"(B1))

__global__ void __launch_bounds__(NTHR, 1)
gemm_kernel() {
    extern __shared__ __align__(1024) char sm[];
    const uint32_t sb  = smem_u32(sm);
    const uint32_t sbA = sb;                    // 2 x 16 KB
    const uint32_t sbB = sb + 2 * TILE_A;       // 2 x 64 KB

    const int tid  = threadIdx.x;
    const int lane = tid & 31;
    const int wid  = tid >> 5;                  // 0..15
    const int wm   = wid >> 3;                  // 0..1: 32 rows each
    const int wn   = wid & 7;                   // 0..7: 32 cols each
    const int row  = tid & 63;
    const int iq   = tid >> 6;                  // 0..7

    const int cta  = blockIdx.x;
    const int gi0  = (GTOT * cta) / NCTA;
    const int gend = (GTOT * (cta + 1)) / NCTA;

    int tt = gi0 / NKT;
    int l  = gi0 - tt * NKT;
    int m0 = (tt & 63) * BM;
    int n0 = (tt >> 6) * BN;

    float acc[2][4][4] = {};
    uint32_t vals[8];
    float xv = 0.0f;

    // ---- global prologue: A(gi0) gen+store, B(gi0) cp, xv for gi0+1
    if (l < BASIS_T) {
        float x0 = g_xT[(size_t)(l * 8 + iq) * BATCH + m0 + row];
        gen_basis(x0, vals);
    } else {
        gen_silu16(l, row, iq, m0, vals);
    }
    sts_vals(sbA + (gi0 & 1) * TILE_A, row, iq, vals);
    cp_B(l, sbB + (gi0 & 1) * TILE_BS, tid, n0);
    asm volatile("cp.async.commit_group;");
    {
        int l1 = l + 1, tt1 = tt;
        if (l1 == NKT) { l1 = 0; tt1++; }
        if (gi0 + 1 < gend && l1 < BASIS_T)
            xv = g_xT[(size_t)(l1 * 8 + iq) * BATCH + (tt1 & 63) * BM + row];
    }
    asm volatile("cp.async.wait_group 0;");
    __syncthreads();

    for (int gi = gi0; gi < gend; gi++) {
        const uint32_t aB = sbA + (gi & 1) * TILE_A;
        const uint32_t bB = sbB + (gi & 1) * TILE_BS;
        const bool havenext = (gi + 1 < gend);

        // next-iteration indices (cross tile boundaries seamlessly)
        int l1 = l + 1, tt1 = tt;
        if (l1 == NKT) { l1 = 0; tt1++; }
        const int m01 = (tt1 & 63) * BM;
        const int n01 = (tt1 >> 6) * BN;

        // 1) B(gi+1) into the other buffer
        if (havenext) cp_B(l1, sbB + ((gi + 1) & 1) * TILE_BS, tid, n01);
        asm volatile("cp.async.commit_group;");

        // 2) generate A(gi+1) into regs
        if (havenext) {
            if (l1 < BASIS_T) gen_basis(xv, vals);
            else              gen_silu16(l1, row, iq, m01, vals);
        }
        // 3) prefetch x for gi+2
        {
            int l2 = l + 2, tt2 = tt;
            if (l2 >= NKT) { l2 -= NKT; tt2++; }
            if (gi + 2 < gend && l2 < BASIS_T)
                xv = g_xT[(size_t)(l2 * 8 + iq) * BATCH + (tt2 & 63) * BM + row];
        }

        // 4) MMA over this k-tile (8 x k16 steps)
#pragma unroll
        for (int ks = 0; ks < 8; ks++) {
            const int c16 = ks * 2 + (lane >> 4);
            uint32_t af[2][4], bf[2][4];
#pragma unroll
            for (int mi = 0; mi < 2; mi++) {
                int r = wm * 32 + mi * 16 + (lane & 15);
                uint32_t u = r * 16 + (c16 ^ (r & 7));
                LDSM_X4(af[mi], aB + u * 16);
            }
#pragma unroll
            for (int nj = 0; nj < 2; nj++) {
                int r = wn * 32 + nj * 16 + (lane & 15);
                uint32_t u = r * 16 + (c16 ^ (r & 7));
                LDSM_X4(bf[nj], bB + u * 16);
            }
#pragma unroll
            for (int mi = 0; mi < 2; mi++)
#pragma unroll
                for (int nj = 0; nj < 2; nj++) {
                    MMA16816(acc[mi][2 * nj],     af[mi], bf[nj][0], bf[nj][2]);
                    MMA16816(acc[mi][2 * nj + 1], af[mi], bf[nj][1], bf[nj][3]);
                }
        }

        // 5) store A(gi+1) into the other A buffer
        if (havenext)
            sts_vals(sbA + ((gi + 1) & 1) * TILE_A, row, iq, vals);

        // 6) tile finished (or last iter)? flush accumulators
        if (l == NKT - 1 || !havenext) {
#pragma unroll
            for (int mi = 0; mi < 2; mi++)
#pragma unroll
                for (int ni = 0; ni < 4; ni++) {
                    int r = m0 + wm * 32 + mi * 16 + (lane >> 2);
                    int c = n0 + wn * 32 + ni * 8 + (lane & 3) * 2;
                    red_add(&g_gemm[(size_t)r * ODIM + c],           acc[mi][ni][0]);
                    red_add(&g_gemm[(size_t)r * ODIM + c + 1],       acc[mi][ni][1]);
                    red_add(&g_gemm[(size_t)(r + 8) * ODIM + c],     acc[mi][ni][2]);
                    red_add(&g_gemm[(size_t)(r + 8) * ODIM + c + 1], acc[mi][ni][3]);
                    acc[mi][ni][0] = 0.f; acc[mi][ni][1] = 0.f;
                    acc[mi][ni][2] = 0.f; acc[mi][ni][3] = 0.f;
                }
        }

        asm volatile("cp.async.wait_group 0;");   // B(gi+1) resident
        __syncthreads();                          // A(gi+1) visible; buffers swap

        l = l1; tt = tt1; m0 = m01; n0 = n01;
    }
}

// -------------------- LayerNorm: 1 warp per row --------------------
__global__ void ln_kernel(const float* __restrict__ gamma,
                          const float* __restrict__ beta,
                          float* __restrict__ out) {
    int warp = threadIdx.x >> 5, lane = threadIdx.x & 31;
    int row = blockIdx.x * 4 + warp;
    const float4* src = (const float4*)&g_gemm[(size_t)row * ODIM];
    float4 v[4];
    float s = 0.0f, s2 = 0.0f;
#pragma unroll
    for (int i = 0; i < 4; i++) {
        v[i] = src[i * 32 + lane];
        s  += v[i].x + v[i].y + v[i].z + v[i].w;
        s2 += v[i].x*v[i].x + v[i].y*v[i].y + v[i].z*v[i].z + v[i].w*v[i].w;
    }
#pragma unroll
    for (int o = 16; o > 0; o >>= 1) {
        s  += __shfl_xor_sync(0xFFFFFFFFu, s,  o);
        s2 += __shfl_xor_sync(0xFFFFFFFFu, s2, o);
    }
    float mean = s * (1.0f / ODIM);
    float var  = s2 * (1.0f / ODIM) - mean * mean;
    float rstd = rsqrtf(var + 1e-5f);
    const float4* g4 = (const float4*)gamma;
    const float4* b4 = (const float4*)beta;
    float4* dst = (float4*)&out[(size_t)row * ODIM];
#pragma unroll
    for (int i = 0; i < 4; i++) {
        int c4 = i * 32 + lane;
        float4 gm = g4[c4], bt = b4[c4], r;
        r.x = (v[i].x - mean) * rstd * gm.x + bt.x;
        r.y = (v[i].y - mean) * rstd * gm.y + bt.y;
        r.z = (v[i].z - mean) * rstd * gm.z + bt.z;
        r.w = (v[i].w - mean) * rstd * gm.w + bt.w;
        dst[c4] = r;
    }
}

// ---------------------------------------------------------------------------
extern "C" void kernel_launch(void* const* d_in, const int* in_sizes, int n_in,
                              void* d_out, int out_size) {
    const float* x      = (const float*)d_in[0];
    const float* wts    = (const float*)d_in[1];
    const float* base_w = (const float*)d_in[2];
    const float* gamma  = (const float*)d_in[3];
    const float* beta   = (const float*)d_in[4];
    float* out = (float*)d_out;

    prep_all<<<CV_BLOCKS + XT_BLOCKS + ZG_BLOCKS, 256>>>(wts, base_w, x);

    int smem_bytes = 2 * TILE_A + 2 * TILE_BS;   // 160 KB
    cudaFuncSetAttribute(gemm_kernel, cudaFuncAttributeMaxDynamicSharedMemorySize,
                         smem_bytes);
    gemm_kernel<<<NCTA, NTHR, smem_bytes>>>();

    ln_kernel<<<BATCH / 4, 128>>>(gamma, beta, out);
}